// round 11
// baseline (speedup 1.0000x reference)
#include <cuda_runtime.h>
#include <cuda_fp16.h>
#include <cstdint>

#define BB 16
#define DD 512
#define TT 4096
#define KK 1024

#define TILE_T 128
#define TILE_K 128
#define N_CHUNKS 64                    // 8 k-chunks x 8 d-subchunks (64 d each)

#define XROWH 136                      // x resident row stride (halfs)
#define CROWH 72                       // cb tile row stride (halfs)
#define CS_STG (TILE_K * CROWH * 2)    // 18432 B per stage

// ---- dynamic smem layout (byte offsets) ----
#define B_XS   0                       // 512 * 136 * 2 = 139264
#define B_CS   139264                  // 2 x 18432 = 36864 -> 176128
#define B_RV1  176128                  // 16x128 f32 = 8192
#define B_RI1  184320
#define B_RV2  192512
#define B_RI2  200704
#define B_BV1  208896                  // 128 f32
#define B_BI1  209408
#define B_BV2  209920
#define B_BI2  210432
#define SMEM_BYTES 210944

#define XS_STRIDE 136                  // rescore float staging stride

__device__ float  g_csq[KK];
__device__ __half g_xh[(size_t)BB * DD * TT];   // fp16 x
__device__ __half g_cbh[KK * DD];               // fp16 codebook

// ---------------- helpers ----------------
__device__ __forceinline__ uint32_t smem_u32(const void* p) {
    uint32_t a;
    asm("{ .reg .u64 t; cvta.to.shared.u64 t, %1; cvt.u32.u64 %0, t; }" : "=r"(a) : "l"(p));
    return a;
}
__device__ __forceinline__ void cp16(uint32_t dst, const void* src) {
    asm volatile("cp.async.cg.shared.global [%0], [%1], 16;" :: "r"(dst), "l"(src));
}
#define CP_COMMIT() asm volatile("cp.async.commit_group;" ::: "memory")
#define CP_WAIT1()  asm volatile("cp.async.wait_group 1;" ::: "memory")
#define CP_WAIT0()  asm volatile("cp.async.wait_group 0;" ::: "memory")

__device__ __forceinline__ void ldsm4(uint32_t* r, uint32_t addr) {
    asm volatile("ldmatrix.sync.aligned.m8n8.x4.shared.b16 {%0,%1,%2,%3}, [%4];"
                 : "=r"(r[0]), "=r"(r[1]), "=r"(r[2]), "=r"(r[3]) : "r"(addr));
}
__device__ __forceinline__ void ldsm2t(uint32_t* r, uint32_t addr) {
    asm volatile("ldmatrix.sync.aligned.m8n8.x2.trans.shared.b16 {%0,%1}, [%2];"
                 : "=r"(r[0]), "=r"(r[1]) : "r"(addr));
}
// D(16x8,f32) += A(16x16 f16) * B(16x8 f16)
__device__ __forceinline__ void mma_f16(float* d, const uint32_t* a, const uint32_t* b) {
    asm volatile(
        "mma.sync.aligned.m16n8k16.row.col.f32.f16.f16.f32 "
        "{%0,%1,%2,%3}, {%4,%5,%6,%7}, {%8,%9}, {%0,%1,%2,%3};"
        : "+f"(d[0]), "+f"(d[1]), "+f"(d[2]), "+f"(d[3])
        : "r"(a[0]), "r"(a[1]), "r"(a[2]), "r"(a[3]), "r"(b[0]), "r"(b[1]));
}
// top-2 update with jnp tie-break (lowest index wins on equal value)
__device__ __forceinline__ void top2(float v, int i, float& v1, int& i1,
                                     float& v2, int& i2) {
    if (v < v1 || (v == v1 && i < i1)) { v2 = v1; i2 = i1; v1 = v; i1 = i; }
    else if (v < v2 || (v == v2 && i < i2)) { v2 = v; i2 = i; }
}

// ---------------------------------------------------------------------------
__global__ void csq_kernel(const float* __restrict__ cb) {
    int warp = (blockIdx.x * blockDim.x + threadIdx.x) >> 5;
    int lane = threadIdx.x & 31;
    if (warp < KK) {
        const float* row = cb + (size_t)warp * DD;
        float s = 0.f;
        #pragma unroll
        for (int d = lane; d < DD; d += 32) { float v = row[d]; s += v * v; }
        #pragma unroll
        for (int o = 16; o; o >>= 1) s += __shfl_xor_sync(0xFFFFFFFFu, s, o);
        if (lane == 0) g_csq[warp] = s;
    }
}

__global__ void prep_half(const float* __restrict__ src, __half* __restrict__ dst,
                          int n8) {
    int i = blockIdx.x * blockDim.x + threadIdx.x;
    if (i < n8) {
        float4 a = ((const float4*)src)[2 * i];
        float4 b = ((const float4*)src)[2 * i + 1];
        __half2 h0 = __floats2half2_rn(a.x, a.y);
        __half2 h1 = __floats2half2_rn(a.z, a.w);
        __half2 h2 = __floats2half2_rn(b.x, b.y);
        __half2 h3 = __floats2half2_rn(b.z, b.w);
        uint4 o;
        o.x = *(uint32_t*)&h0; o.y = *(uint32_t*)&h1;
        o.z = *(uint32_t*)&h2; o.w = *(uint32_t*)&h3;
        ((uint4*)dst)[i] = o;
    }
}

// ---------------------------------------------------------------------------
// x-resident fp16 HMMA screen -> top-2 -> exact fp32 rescore -> gather.
// x tile [512d x 128t] loaded ONCE; cb streamed in 64-d double-buffered chunks.
// 8 warps: warp_k = wid>>2 (2 x 64k), warp_t = wid&3 (4 x 32t).
// ---------------------------------------------------------------------------
__global__ __launch_bounds__(256, 1)
void vq_kernel(const float* __restrict__ x, const float* __restrict__ cb,
               float* __restrict__ qout, float* __restrict__ iout) {
    extern __shared__ char smb[];
    float* rv1 = (float*)(smb + B_RV1);  int* ri1 = (int*)(smb + B_RI1);
    float* rv2 = (float*)(smb + B_RV2);  int* ri2 = (int*)(smb + B_RI2);
    float* bv1 = (float*)(smb + B_BV1);  int* bi1 = (int*)(smb + B_BI1);
    float* bv2 = (float*)(smb + B_BV2);  int* bi2 = (int*)(smb + B_BI2);

    const int tid    = threadIdx.x;
    const int wid    = tid >> 5;
    const int lane   = tid & 31;
    const int gid    = lane >> 2;
    const int tig    = lane & 3;
    const int warp_k = wid >> 2;
    const int warp_t = wid & 3;
    const int kwb    = warp_k * 64;
    const int twb    = warp_t * 32;
    const int lm_k   = lane & 15;
    const int lm_d8  = (lane & 16) >> 1;   // 0 or 8 (halfs)

    const int blk = blockIdx.x;
    const int b   = blk >> 5;
    const int t0  = (blk & 31) << 7;

    const float*  xb  = x + (size_t)b * DD * TT + t0;      // raw (rescore)
    const __half* xhb = g_xh + (size_t)b * DD * TT + t0;   // fp16 (screen)

    const uint32_t sb   = smem_u32(smb);
    const uint32_t xs_u = sb + B_XS;
    const uint32_t cs_u = sb + B_CS;

    if (tid < TILE_T) { bv1[tid] = 3.4e38f; bi1[tid] = 0;
                        bv2[tid] = 3.4e38f; bi2[tid] = 0; }

    // ---- one-time x fill: 512 rows x 128 halfs, 8192 cp.async ----
    #pragma unroll
    for (int l = 0; l < 32; l++) {
        int e  = l * 256 + tid;
        int d  = e >> 4;
        int t8 = e & 15;
        cp16(xs_u + (uint32_t)((d * XROWH + t8 * 8) * 2),
             xhb + (size_t)d * TT + t8 * 8);
    }
    CP_COMMIT();

    // ---- cb chunk issue: chunk c -> k0=(c>>3)*128, d0=(c&7)*64 ----
    auto issue = [&](int c, int s) {
        const int k0 = (c >> 3) << 7;
        const int d0 = (c & 7) << 6;
        const uint32_t cdst = cs_u + (uint32_t)(s * CS_STG);
        #pragma unroll
        for (int l = 0; l < 4; l++) {            // 128k x 64d halfs, 1024 ops
            int e  = l * 256 + tid;
            int k  = e >> 3;
            int dq = e & 7;
            cp16(cdst + (uint32_t)((k * CROWH + dq * 8) * 2),
                 g_cbh + (size_t)(k0 + k) * DD + d0 + dq * 8);
        }
        CP_COMMIT();
    };

    float acc[4][4][4];
    #pragma unroll
    for (int m = 0; m < 4; m++)
        #pragma unroll
        for (int n = 0; n < 4; n++)
            #pragma unroll
            for (int r = 0; r < 4; r++) acc[m][n][r] = 0.f;

    issue(0, 0);

    for (int c = 0; c < N_CHUNKS; c++) {
        const int s = c & 1;
        if (c + 1 < N_CHUNKS) issue(c + 1, s ^ 1);
        if (c + 1 < N_CHUNKS) { CP_WAIT1(); } else { CP_WAIT0(); }
        __syncthreads();

        const uint32_t csS  = cs_u + (uint32_t)(s * CS_STG);
        const int      dbase = (c & 7) << 6;

        #pragma unroll
        for (int ds = 0; ds < 4; ds++) {         // four k16 steps cover 64 d
            uint32_t af[4][4];
            #pragma unroll
            for (int m = 0; m < 4; m++)
                ldsm4(af[m], csS +
                    (uint32_t)(((kwb + m * 16 + lm_k) * CROWH + ds * 16 + lm_d8) * 2));
            #pragma unroll
            for (int n = 0; n < 4; n++) {
                uint32_t bf[2];
                ldsm2t(bf, xs_u +
                    (uint32_t)(((dbase + ds * 16 + lm_k) * XROWH + twb + n * 8) * 2));
                #pragma unroll
                for (int m = 0; m < 4; m++) mma_f16(acc[m][n], af[m], bf);
            }
        }

        // ---- end of a k-chunk: fold top-2 (rows=k, cols=t), merge, reset ----
        if ((c & 7) == 7) {
            const int k0p  = (c >> 3) << 7;
            const int slot = warp_k * 8 + gid;
            const int kb   = k0p + kwb;
            #pragma unroll
            for (int n = 0; n < 4; n++) {
                const int te = twb + n * 8 + 2 * tig;
                float v1e = 3.4e38f, v2e = 3.4e38f; int i1e = 0, i2e = 0;
                float v1o = 3.4e38f, v2o = 3.4e38f; int i1o = 0, i2o = 0;
                #pragma unroll
                for (int m = 0; m < 4; m++) {
                    const int kA = kb + m * 16 + gid;
                    const float cqA = __ldg(&g_csq[kA]);
                    const float cqB = __ldg(&g_csq[kA + 8]);
                    top2(cqA - 2.f * acc[m][n][0], kA,     v1e, i1e, v2e, i2e);
                    top2(cqB - 2.f * acc[m][n][2], kA + 8, v1e, i1e, v2e, i2e);
                    top2(cqA - 2.f * acc[m][n][1], kA,     v1o, i1o, v2o, i2o);
                    top2(cqB - 2.f * acc[m][n][3], kA + 8, v1o, i1o, v2o, i2o);
                }
                rv1[slot * 128 + te] = v1e;     ri1[slot * 128 + te] = i1e;
                rv2[slot * 128 + te] = v2e;     ri2[slot * 128 + te] = i2e;
                rv1[slot * 128 + te + 1] = v1o; ri1[slot * 128 + te + 1] = i1o;
                rv2[slot * 128 + te + 1] = v2o; ri2[slot * 128 + te + 1] = i2o;
            }
            #pragma unroll
            for (int m = 0; m < 4; m++)
                #pragma unroll
                for (int n = 0; n < 4; n++)
                    #pragma unroll
                    for (int r = 0; r < 4; r++) acc[m][n][r] = 0.f;
            __syncthreads();
            if (tid < TILE_T) {
                float v1 = bv1[tid], v2 = bv2[tid];
                int   i1 = bi1[tid], i2 = bi2[tid];
                #pragma unroll
                for (int r = 0; r < 16; r++) {
                    top2(rv1[r * 128 + tid], ri1[r * 128 + tid], v1, i1, v2, i2);
                    top2(rv2[r * 128 + tid], ri2[r * 128 + tid], v1, i1, v2, i2);
                }
                bv1[tid] = v1; bi1[tid] = i1; bv2[tid] = v2; bi2[tid] = i2;
            }
        }
        __syncthreads();
    }

    // ---- exact fp32 rescore of top-2 candidates (raw x, raw cb) ----
    float* XSf = (float*)smb;                    // reuse x region as f32 staging
    const int p    = tid >> 1;
    const int half = tid & 1;
    const int cand = half ? bi2[p] : bi1[p];
    const float* crow = cb + (size_t)cand * DD;
    float dot = 0.f;
    for (int dc = 0; dc < 16; dc++) {
        const int d0 = dc * 32;
        __syncthreads();
        #pragma unroll
        for (int l = 0; l < 4; l++) {
            int e  = l * 256 + tid;
            int d  = e >> 5;
            int t4 = e & 31;
            *(float4*)&XSf[d * XS_STRIDE + t4 * 4] =
                *(const float4*)(xb + (size_t)(d0 + d) * TT + t4 * 4);
        }
        __syncthreads();
        #pragma unroll
        for (int j = 0; j < 8; j++) {
            float4 cv = *(const float4*)(crow + d0 + 4 * j);
            dot = fmaf(XSf[(4 * j + 0) * XS_STRIDE + p], cv.x, dot);
            dot = fmaf(XSf[(4 * j + 1) * XS_STRIDE + p], cv.y, dot);
            dot = fmaf(XSf[(4 * j + 2) * XS_STRIDE + p], cv.z, dot);
            dot = fmaf(XSf[(4 * j + 3) * XS_STRIDE + p], cv.w, dot);
        }
    }
    rv1[tid] = __ldg(&g_csq[cand]) - 2.f * dot;
    __syncthreads();
    if (tid < TILE_T) {
        float sA = rv1[2 * tid], sB = rv1[2 * tid + 1];
        int   iA = bi1[tid],     iB = bi2[tid];
        int fin = (sB < sA || (sB == sA && iB < iA)) ? iB : iA;
        bi1[tid] = fin;
        iout[(size_t)b * TT + t0 + tid] = (float)fin;
    }
    __syncthreads();

    // ---- gather quantized: t-coalesced stores ----
    float* qb = qout + (size_t)b * DD * TT + t0;
    for (int e = tid; e < DD * TILE_T; e += 256) {
        int t = e & (TILE_T - 1);
        int d = e >> 7;
        qb[(size_t)d * TT + t] = cb[(size_t)bi1[t] * DD + d];
    }
}

extern "C" void kernel_launch(void* const* d_in, const int* in_sizes, int n_in,
                              void* d_out, int out_size) {
    const float* x  = (const float*)d_in[0];   // [B, D, T] fp32
    const float* cb = (const float*)d_in[1];   // [K, D]    fp32

    float* qout = (float*)d_out;                         // [B, D, T]
    float* iout = (float*)d_out + (size_t)BB * DD * TT;  // [B, T] as float

    cudaFuncSetAttribute(vq_kernel, cudaFuncAttributeMaxDynamicSharedMemorySize,
                         SMEM_BYTES);

    __half* xh;  cudaGetSymbolAddress((void**)&xh,  g_xh);
    __half* cbh; cudaGetSymbolAddress((void**)&cbh, g_cbh);

    csq_kernel<<<(KK * 32 + 255) / 256, 256>>>(cb);
    {
        int n8 = (BB * DD * TT) / 8;
        prep_half<<<(n8 + 255) / 256, 256>>>(x, xh, n8);
    }
    {
        int n8 = (KK * DD) / 8;
        prep_half<<<(n8 + 255) / 256, 256>>>(cb, cbh, n8);
    }
    vq_kernel<<<(BB * TT) / TILE_T, 256, SMEM_BYTES>>>(x, cb, qout, iout);
}

// round 13
// speedup vs baseline: 1.2331x; 1.2331x over previous
#include <cuda_runtime.h>
#include <cuda_fp16.h>
#include <cstdint>

#define BB 16
#define DD 512
#define TT 4096
#define KK 1024

#define TILE_T 64                      // t per CTA
#define TILE_K 128                     // k per pass
#define N_CHUNKS 128                   // 8 k-passes x 16 d-chunks (32 d)

#define XROWH 72                       // x tile row stride (halfs), conflict-free
#define CROWH 40                       // cb tile row stride (halfs), conflict-free
#define XS_STG (32 * XROWH * 2)        // 4608 B per stage
#define CS_STG (TILE_K * CROWH * 2)    // 10240 B per stage

// ---- dynamic smem layout (byte offsets) ----
#define B_XS   0                       // 2 x 4608  = 9216
#define B_CS   9216                    // 2 x 10240 = 20480 -> 29696
#define B_RV1  29696                   // [2][64] f32 = 512
#define B_RI1  30208
#define B_RV2  30720
#define B_RI2  31232
#define B_BV1  31744                   // 64 f32
#define B_BI1  32000
#define B_BV2  32256
#define B_BI2  32512
#define SMEM_BYTES 32768

__device__ float  g_csq[KK];
__device__ __half g_xh[(size_t)BB * DD * TT];   // fp16 x
__device__ __half g_cbh[KK * DD];               // fp16 codebook

// ---------------- helpers ----------------
__device__ __forceinline__ uint32_t smem_u32(const void* p) {
    uint32_t a;
    asm("{ .reg .u64 t; cvta.to.shared.u64 t, %1; cvt.u32.u64 %0, t; }" : "=r"(a) : "l"(p));
    return a;
}
__device__ __forceinline__ void cp16(uint32_t dst, const void* src) {
    asm volatile("cp.async.cg.shared.global [%0], [%1], 16;" :: "r"(dst), "l"(src));
}
#define CP_COMMIT() asm volatile("cp.async.commit_group;" ::: "memory")
#define CP_WAIT1()  asm volatile("cp.async.wait_group 1;" ::: "memory")
#define CP_WAIT0()  asm volatile("cp.async.wait_group 0;" ::: "memory")

__device__ __forceinline__ void ldsm4(uint32_t* r, uint32_t addr) {
    asm volatile("ldmatrix.sync.aligned.m8n8.x4.shared.b16 {%0,%1,%2,%3}, [%4];"
                 : "=r"(r[0]), "=r"(r[1]), "=r"(r[2]), "=r"(r[3]) : "r"(addr));
}
__device__ __forceinline__ void ldsm2t(uint32_t* r, uint32_t addr) {
    asm volatile("ldmatrix.sync.aligned.m8n8.x2.trans.shared.b16 {%0,%1}, [%2];"
                 : "=r"(r[0]), "=r"(r[1]) : "r"(addr));
}
// D(16x8,f32) += A(16x16 f16) * B(16x8 f16)
__device__ __forceinline__ void mma_f16(float* d, const uint32_t* a, const uint32_t* b) {
    asm volatile(
        "mma.sync.aligned.m16n8k16.row.col.f32.f16.f16.f32 "
        "{%0,%1,%2,%3}, {%4,%5,%6,%7}, {%8,%9}, {%0,%1,%2,%3};"
        : "+f"(d[0]), "+f"(d[1]), "+f"(d[2]), "+f"(d[3])
        : "r"(a[0]), "r"(a[1]), "r"(a[2]), "r"(a[3]), "r"(b[0]), "r"(b[1]));
}
// top-2 update with jnp tie-break (lowest index wins on equal value)
__device__ __forceinline__ void top2(float v, int i, float& v1, int& i1,
                                     float& v2, int& i2) {
    if (v < v1 || (v == v1 && i < i1)) { v2 = v1; i2 = i1; v1 = v; i1 = i; }
    else if (v < v2 || (v == v2 && i < i2)) { v2 = v; i2 = i; }
}

// ---------------------------------------------------------------------------
__global__ void csq_kernel(const float* __restrict__ cb) {
    int warp = (blockIdx.x * blockDim.x + threadIdx.x) >> 5;
    int lane = threadIdx.x & 31;
    if (warp < KK) {
        const float* row = cb + (size_t)warp * DD;
        float s = 0.f;
        #pragma unroll
        for (int d = lane; d < DD; d += 32) { float v = row[d]; s += v * v; }
        #pragma unroll
        for (int o = 16; o; o >>= 1) s += __shfl_xor_sync(0xFFFFFFFFu, s, o);
        if (lane == 0) g_csq[warp] = s;
    }
}

__global__ void prep_half(const float* __restrict__ src, __half* __restrict__ dst,
                          int n8) {
    int i = blockIdx.x * blockDim.x + threadIdx.x;
    if (i < n8) {
        float4 a = ((const float4*)src)[2 * i];
        float4 b = ((const float4*)src)[2 * i + 1];
        __half2 h0 = __floats2half2_rn(a.x, a.y);
        __half2 h1 = __floats2half2_rn(a.z, a.w);
        __half2 h2 = __floats2half2_rn(b.x, b.y);
        __half2 h3 = __floats2half2_rn(b.z, b.w);
        uint4 o;
        o.x = *(uint32_t*)&h0; o.y = *(uint32_t*)&h1;
        o.z = *(uint32_t*)&h2; o.w = *(uint32_t*)&h3;
        ((uint4*)dst)[i] = o;
    }
}

// ---------------------------------------------------------------------------
// fp16 HMMA screen (low-reg tiles, shuffle top-2 fold) -> exact rescore.
// CTA: 64 t x full K. 8 warps: warp_k = wid>>2 (2 x 64k), warp_t = wid&3 (4 x 16t).
// acc[m][n][r]: m = 4 k-subtiles of 16, n = 2 t-subtiles of 8. 32 regs.
// ---------------------------------------------------------------------------
__global__ __launch_bounds__(256, 3)
void vq_kernel(const float* __restrict__ x, const float* __restrict__ cb,
               float* __restrict__ qout, float* __restrict__ iout) {
    extern __shared__ char smb[];
    float* rv1 = (float*)(smb + B_RV1);  int* ri1 = (int*)(smb + B_RI1);
    float* rv2 = (float*)(smb + B_RV2);  int* ri2 = (int*)(smb + B_RI2);
    float* bv1 = (float*)(smb + B_BV1);  int* bi1 = (int*)(smb + B_BI1);
    float* bv2 = (float*)(smb + B_BV2);  int* bi2 = (int*)(smb + B_BI2);

    const int tid    = threadIdx.x;
    const int wid    = tid >> 5;
    const int lane   = tid & 31;
    const int gid    = lane >> 2;       // 0..7
    const int tig    = lane & 3;        // 0..3
    const int warp_k = wid >> 2;        // 0..1 (64 k each)
    const int warp_t = wid & 3;         // 0..3 (16 t each)
    const int kwb    = warp_k * 64;
    const int twb    = warp_t * 16;
    const int lm_k   = lane & 15;
    const int lm_d8  = (lane & 16) >> 1;   // 0 or 8 (halfs)

    const int blk = blockIdx.x;
    const int b   = blk >> 6;           // 64 t-tiles per batch
    const int t0  = (blk & 63) << 6;

    const float*  xb  = x + (size_t)b * DD * TT + t0;      // raw (rescore)
    const __half* xhb = g_xh + (size_t)b * DD * TT + t0;   // fp16 (screen)

    const uint32_t sb   = smem_u32(smb);
    const uint32_t xs_u = sb + B_XS;
    const uint32_t cs_u = sb + B_CS;

    if (tid < TILE_T) { bv1[tid] = 3.4e38f; bi1[tid] = 0;
                        bv2[tid] = 3.4e38f; bi2[tid] = 0; }

    // ---- issue chunk c: k0=(c>>4)*128, d0=(c&15)*32 ----
    auto issue = [&](int c, int s) {
        const int k0 = (c >> 4) << 7;
        const int d0 = (c & 15) << 5;
        // x: 32d x 64t halfs = 256 x 16B
        {
            int d  = tid >> 3;
            int t8 = tid & 7;
            cp16(xs_u + (uint32_t)(s * XS_STG) + (uint32_t)((d * XROWH + t8 * 8) * 2),
                 xhb + (size_t)(d0 + d) * TT + t8 * 8);
        }
        // cb: 128k x 32d halfs = 512 x 16B
        #pragma unroll
        for (int l = 0; l < 2; l++) {
            int e  = l * 256 + tid;
            int k  = e >> 2;
            int dq = e & 3;
            cp16(cs_u + (uint32_t)(s * CS_STG) + (uint32_t)((k * CROWH + dq * 8) * 2),
                 g_cbh + (size_t)(k0 + k) * DD + d0 + dq * 8);
        }
        CP_COMMIT();
    };

    float acc[4][2][4];
    #pragma unroll
    for (int m = 0; m < 4; m++)
        #pragma unroll
        for (int n = 0; n < 2; n++)
            #pragma unroll
            for (int r = 0; r < 4; r++) acc[m][n][r] = 0.f;

    issue(0, 0);

    for (int c = 0; c < N_CHUNKS; c++) {
        const int s = c & 1;
        if (c + 1 < N_CHUNKS) issue(c + 1, s ^ 1);
        if (c + 1 < N_CHUNKS) { CP_WAIT1(); } else { CP_WAIT0(); }
        __syncthreads();

        const uint32_t xsS = xs_u + (uint32_t)(s * XS_STG);
        const uint32_t csS = cs_u + (uint32_t)(s * CS_STG);

        #pragma unroll
        for (int ds = 0; ds < 2; ds++) {         // two k16 steps cover 32 d
            uint32_t af[4][4];
            #pragma unroll
            for (int m = 0; m < 4; m++)
                ldsm4(af[m], csS +
                    (uint32_t)(((kwb + m * 16 + lm_k) * CROWH + ds * 16 + lm_d8) * 2));
            #pragma unroll
            for (int n = 0; n < 2; n++) {
                uint32_t bf[2];
                ldsm2t(bf, xsS +
                    (uint32_t)(((ds * 16 + lm_k) * XROWH + twb + n * 8) * 2));
                #pragma unroll
                for (int m = 0; m < 4; m++) mma_f16(acc[m][n], af[m], bf);
            }
        }

        // ---- end of a k-pass: shuffle top-2 fold, merge, reset ----
        if ((c & 15) == 15) {
            const int k0p = (c >> 4) << 7;
            const int kb  = k0p + kwb;
            #pragma unroll
            for (int n = 0; n < 2; n++) {
                #pragma unroll
                for (int h = 0; h < 2; h++) {
                    float v1 = 3.4e38f, v2 = 3.4e38f;
                    int   i1 = 0,       i2 = 0;
                    #pragma unroll
                    for (int m = 0; m < 4; m++) {
                        const int kA = kb + m * 16 + gid;
                        top2(__ldg(&g_csq[kA])     - 2.f * acc[m][n][h],     kA,
                             v1, i1, v2, i2);
                        top2(__ldg(&g_csq[kA + 8]) - 2.f * acc[m][n][h + 2], kA + 8,
                             v1, i1, v2, i2);
                    }
                    // fold across gid (lanes tig, tig+4, ..., tig+28)
                    #pragma unroll
                    for (int off = 4; off <= 16; off <<= 1) {
                        float ov1 = __shfl_xor_sync(0xFFFFFFFFu, v1, off);
                        int   oi1 = __shfl_xor_sync(0xFFFFFFFFu, i1, off);
                        float ov2 = __shfl_xor_sync(0xFFFFFFFFu, v2, off);
                        int   oi2 = __shfl_xor_sync(0xFFFFFFFFu, i2, off);
                        top2(ov1, oi1, v1, i1, v2, i2);
                        top2(ov2, oi2, v1, i1, v2, i2);
                    }
                    if (gid == 0) {
                        const int t = twb + n * 8 + 2 * tig + h;
                        rv1[warp_k * 64 + t] = v1; ri1[warp_k * 64 + t] = i1;
                        rv2[warp_k * 64 + t] = v2; ri2[warp_k * 64 + t] = i2;
                    }
                }
            }
            #pragma unroll
            for (int m = 0; m < 4; m++)
                #pragma unroll
                for (int n = 0; n < 2; n++)
                    #pragma unroll
                    for (int r = 0; r < 4; r++) acc[m][n][r] = 0.f;
            __syncthreads();
            if (tid < TILE_T) {
                float v1 = bv1[tid], v2 = bv2[tid];
                int   i1 = bi1[tid], i2 = bi2[tid];
                top2(rv1[tid],      ri1[tid],      v1, i1, v2, i2);
                top2(rv2[tid],      ri2[tid],      v1, i1, v2, i2);
                top2(rv1[64 + tid], ri1[64 + tid], v1, i1, v2, i2);
                top2(rv2[64 + tid], ri2[64 + tid], v1, i1, v2, i2);
                bv1[tid] = v1; bi1[tid] = i1; bv2[tid] = v2; bi2[tid] = i2;
            }
        }
        __syncthreads();
    }

    // ---- exact fp32 rescore of top-2 candidates (raw x, raw cb) ----
    float* XSf = (float*)smb;                    // f32 staging, 32 x 72 floats
    float* rsc = rv1;                            // 128 scores
    const int p    = (tid & 127) >> 1;
    const int half = tid & 1;
    const int cand = half ? bi2[p] : bi1[p];
    const float* crow = cb + (size_t)cand * DD;
    float dot = 0.f;
    for (int dc = 0; dc < 16; dc++) {
        const int d0 = dc * 32;
        __syncthreads();
        #pragma unroll
        for (int l = 0; l < 2; l++) {            // 32d x 64t floats = 512 f4
            int e  = l * 256 + tid;
            int d  = e >> 4;
            int t4 = e & 15;
            *(float4*)&XSf[d * XROWH + t4 * 4] =
                *(const float4*)(xb + (size_t)(d0 + d) * TT + t4 * 4);
        }
        __syncthreads();
        if (tid < 128) {
            #pragma unroll
            for (int j = 0; j < 8; j++) {
                float4 cv = *(const float4*)(crow + d0 + 4 * j);
                dot = fmaf(XSf[(4 * j + 0) * XROWH + p], cv.x, dot);
                dot = fmaf(XSf[(4 * j + 1) * XROWH + p], cv.y, dot);
                dot = fmaf(XSf[(4 * j + 2) * XROWH + p], cv.z, dot);
                dot = fmaf(XSf[(4 * j + 3) * XROWH + p], cv.w, dot);
            }
        }
    }
    if (tid < 128) rsc[tid] = __ldg(&g_csq[cand]) - 2.f * dot;
    __syncthreads();
    if (tid < TILE_T) {
        float sA = rsc[2 * tid], sB = rsc[2 * tid + 1];
        int   iA = bi1[tid],     iB = bi2[tid];
        int fin = (sB < sA || (sB == sA && iB < iA)) ? iB : iA;
        bi1[tid] = fin;
        iout[(size_t)b * TT + t0 + tid] = (float)fin;
    }
    __syncthreads();

    // ---- gather quantized: t-coalesced stores ----
    float* qb = qout + (size_t)b * DD * TT + t0;
    for (int e = tid; e < DD * TILE_T; e += 256) {
        int t = e & (TILE_T - 1);
        int d = e >> 6;
        qb[(size_t)d * TT + t] = cb[(size_t)bi1[t] * DD + d];
    }
}

extern "C" void kernel_launch(void* const* d_in, const int* in_sizes, int n_in,
                              void* d_out, int out_size) {
    const float* x  = (const float*)d_in[0];   // [B, D, T] fp32
    const float* cb = (const float*)d_in[1];   // [K, D]    fp32

    float* qout = (float*)d_out;                         // [B, D, T]
    float* iout = (float*)d_out + (size_t)BB * DD * TT;  // [B, T] as float

    cudaFuncSetAttribute(vq_kernel, cudaFuncAttributeMaxDynamicSharedMemorySize,
                         SMEM_BYTES);

    __half* xh;  cudaGetSymbolAddress((void**)&xh,  g_xh);
    __half* cbh; cudaGetSymbolAddress((void**)&cbh, g_cbh);

    csq_kernel<<<(KK * 32 + 255) / 256, 256>>>(cb);
    {
        int n8 = (BB * DD * TT) / 8;
        prep_half<<<(n8 + 255) / 256, 256>>>(x, xh, n8);
    }
    {
        int n8 = (KK * DD) / 8;
        prep_half<<<(n8 + 255) / 256, 256>>>(cb, cbh, n8);
    }
    vq_kernel<<<(BB * TT) / TILE_T, 256, SMEM_BYTES>>>(x, cb, qout, iout);
}

// round 15
// speedup vs baseline: 1.2496x; 1.0134x over previous
#include <cuda_runtime.h>
#include <cuda_fp16.h>
#include <cstdint>

#define BB 16
#define DD 512
#define TT 4096
#define KK 1024

#define TILE_T 64                      // t per CTA
#define TILE_K 128                     // k per pass
#define N_CHUNKS 128                   // 8 k-passes x 16 d-chunks (32 d)

#define XROWH 72                       // x tile row stride (halfs)
#define CROWH 40                       // cb tile row stride (halfs)
#define XS_STG (32 * XROWH * 2)        // 4608 B per stage
#define CS_STG (TILE_K * CROWH * 2)    // 10240 B per stage

// ---- dynamic smem layout (byte offsets), 4 pipeline stages ----
#define B_XS   0                       // 4 x 4608  = 18432
#define B_CS   18432                   // 4 x 10240 = 40960 -> 59392
#define B_RV1  59392                   // [2][64] f32 = 512
#define B_RI1  59904
#define B_RV2  60416
#define B_RI2  60928
#define B_BV1  61440                   // 64 f32
#define B_BI1  61696
#define B_BV2  61952
#define B_BI2  62208
#define SMEM_BYTES 62464

__device__ float  g_csq[KK];
__device__ __half g_xh[(size_t)BB * DD * TT];   // fp16 x
__device__ __half g_cbh[KK * DD];               // fp16 codebook

// ---------------- helpers ----------------
__device__ __forceinline__ uint32_t smem_u32(const void* p) {
    uint32_t a;
    asm("{ .reg .u64 t; cvta.to.shared.u64 t, %1; cvt.u32.u64 %0, t; }" : "=r"(a) : "l"(p));
    return a;
}
__device__ __forceinline__ void cp16(uint32_t dst, const void* src) {
    asm volatile("cp.async.cg.shared.global [%0], [%1], 16;" :: "r"(dst), "l"(src));
}
#define CP_COMMIT() asm volatile("cp.async.commit_group;" ::: "memory")
#define CP_WAIT2()  asm volatile("cp.async.wait_group 2;" ::: "memory")

__device__ __forceinline__ void ldsm4(uint32_t* r, uint32_t addr) {
    asm volatile("ldmatrix.sync.aligned.m8n8.x4.shared.b16 {%0,%1,%2,%3}, [%4];"
                 : "=r"(r[0]), "=r"(r[1]), "=r"(r[2]), "=r"(r[3]) : "r"(addr));
}
__device__ __forceinline__ void ldsm2t(uint32_t* r, uint32_t addr) {
    asm volatile("ldmatrix.sync.aligned.m8n8.x2.trans.shared.b16 {%0,%1}, [%2];"
                 : "=r"(r[0]), "=r"(r[1]) : "r"(addr));
}
// D(16x8,f32) += A(16x16 f16) * B(16x8 f16)
__device__ __forceinline__ void mma_f16(float* d, const uint32_t* a, const uint32_t* b) {
    asm volatile(
        "mma.sync.aligned.m16n8k16.row.col.f32.f16.f16.f32 "
        "{%0,%1,%2,%3}, {%4,%5,%6,%7}, {%8,%9}, {%0,%1,%2,%3};"
        : "+f"(d[0]), "+f"(d[1]), "+f"(d[2]), "+f"(d[3])
        : "r"(a[0]), "r"(a[1]), "r"(a[2]), "r"(a[3]), "r"(b[0]), "r"(b[1]));
}
// top-2 update with jnp tie-break (lowest index wins on equal value)
__device__ __forceinline__ void top2(float v, int i, float& v1, int& i1,
                                     float& v2, int& i2) {
    if (v < v1 || (v == v1 && i < i1)) { v2 = v1; i2 = i1; v1 = v; i1 = i; }
    else if (v < v2 || (v == v2 && i < i2)) { v2 = v; i2 = i; }
}

// ---------------------------------------------------------------------------
__global__ void csq_kernel(const float* __restrict__ cb) {
    int warp = (blockIdx.x * blockDim.x + threadIdx.x) >> 5;
    int lane = threadIdx.x & 31;
    if (warp < KK) {
        const float* row = cb + (size_t)warp * DD;
        float s = 0.f;
        #pragma unroll
        for (int d = lane; d < DD; d += 32) { float v = row[d]; s += v * v; }
        #pragma unroll
        for (int o = 16; o; o >>= 1) s += __shfl_xor_sync(0xFFFFFFFFu, s, o);
        if (lane == 0) g_csq[warp] = s;
    }
}

__global__ void prep_half(const float* __restrict__ src, __half* __restrict__ dst,
                          int n8) {
    int i = blockIdx.x * blockDim.x + threadIdx.x;
    if (i < n8) {
        float4 a = ((const float4*)src)[2 * i];
        float4 b = ((const float4*)src)[2 * i + 1];
        __half2 h0 = __floats2half2_rn(a.x, a.y);
        __half2 h1 = __floats2half2_rn(a.z, a.w);
        __half2 h2 = __floats2half2_rn(b.x, b.y);
        __half2 h3 = __floats2half2_rn(b.z, b.w);
        uint4 o;
        o.x = *(uint32_t*)&h0; o.y = *(uint32_t*)&h1;
        o.z = *(uint32_t*)&h2; o.w = *(uint32_t*)&h3;
        ((uint4*)dst)[i] = o;
    }
}

// ---------------------------------------------------------------------------
// fp16 HMMA screen, 4-stage cp.async pipeline, ONE sync per chunk.
// CTA: 64 t x full K. 8 warps: warp_k = wid>>2 (2 x 64k), warp_t = wid&3 (4 x 16t).
// ---------------------------------------------------------------------------
__global__ __launch_bounds__(256, 3)
void vq_kernel(const float* __restrict__ x, const float* __restrict__ cb,
               float* __restrict__ qout, float* __restrict__ iout) {
    extern __shared__ char smb[];
    float* rv1 = (float*)(smb + B_RV1);  int* ri1 = (int*)(smb + B_RI1);
    float* rv2 = (float*)(smb + B_RV2);  int* ri2 = (int*)(smb + B_RI2);
    float* bv1 = (float*)(smb + B_BV1);  int* bi1 = (int*)(smb + B_BI1);
    float* bv2 = (float*)(smb + B_BV2);  int* bi2 = (int*)(smb + B_BI2);

    const int tid    = threadIdx.x;
    const int wid    = tid >> 5;
    const int lane   = tid & 31;
    const int gid    = lane >> 2;       // 0..7
    const int tig    = lane & 3;        // 0..3
    const int warp_k = wid >> 2;        // 0..1 (64 k each)
    const int warp_t = wid & 3;         // 0..3 (16 t each)
    const int kwb    = warp_k * 64;
    const int twb    = warp_t * 16;
    const int lm_k   = lane & 15;
    const int lm_d8  = (lane & 16) >> 1;   // 0 or 8 (halfs)

    const int blk = blockIdx.x;
    const int b   = blk >> 6;           // 64 t-tiles per batch
    const int t0  = (blk & 63) << 6;

    const float*  xb  = x + (size_t)b * DD * TT + t0;      // raw (rescore)
    const __half* xhb = g_xh + (size_t)b * DD * TT + t0;   // fp16 (screen)

    const uint32_t sb   = smem_u32(smb);
    const uint32_t xs_u = sb + B_XS;
    const uint32_t cs_u = sb + B_CS;

    if (tid < TILE_T) { bv1[tid] = 3.4e38f; bi1[tid] = 0;
                        bv2[tid] = 3.4e38f; bi2[tid] = 0; }

    // ---- issue chunk c into stage c&3; ALWAYS commits (empty past end) ----
    auto issue = [&](int c) {
        if (c < N_CHUNKS) {
            const int s  = c & 3;
            const int k0 = (c >> 4) << 7;
            const int d0 = (c & 15) << 5;
            // x: 32d x 64t halfs = 256 x 16B
            {
                int d  = tid >> 3;
                int t8 = tid & 7;
                cp16(xs_u + (uint32_t)(s * XS_STG) +
                         (uint32_t)((d * XROWH + t8 * 8) * 2),
                     xhb + (size_t)(d0 + d) * TT + t8 * 8);
            }
            // cb: 128k x 32d halfs = 512 x 16B
            #pragma unroll
            for (int l = 0; l < 2; l++) {
                int e  = l * 256 + tid;
                int k  = e >> 2;
                int dq = e & 3;
                cp16(cs_u + (uint32_t)(s * CS_STG) +
                         (uint32_t)((k * CROWH + dq * 8) * 2),
                     g_cbh + (size_t)(k0 + k) * DD + d0 + dq * 8);
            }
        }
        CP_COMMIT();
    };

    float acc[4][2][4];
    #pragma unroll
    for (int m = 0; m < 4; m++)
        #pragma unroll
        for (int n = 0; n < 2; n++)
            #pragma unroll
            for (int r = 0; r < 4; r++) acc[m][n][r] = 0.f;

    issue(0); issue(1); issue(2);

    for (int c = 0; c < N_CHUNKS; c++) {
        CP_WAIT2();            // group c complete (pending <= {c+1, c+2})
        __syncthreads();       // visibility + all warps done with iter c-1
        issue(c + 3);          // overwrite target last read at iter c-1: safe

        const int s = c & 3;
        const uint32_t xsS = xs_u + (uint32_t)(s * XS_STG);
        const uint32_t csS = cs_u + (uint32_t)(s * CS_STG);

        #pragma unroll
        for (int ds = 0; ds < 2; ds++) {         // two k16 steps cover 32 d
            uint32_t af[4][4];
            #pragma unroll
            for (int m = 0; m < 4; m++)
                ldsm4(af[m], csS +
                    (uint32_t)(((kwb + m * 16 + lm_k) * CROWH + ds * 16 + lm_d8) * 2));
            #pragma unroll
            for (int n = 0; n < 2; n++) {
                uint32_t bf[2];
                ldsm2t(bf, xsS +
                    (uint32_t)(((ds * 16 + lm_k) * XROWH + twb + n * 8) * 2));
                #pragma unroll
                for (int m = 0; m < 4; m++) mma_f16(acc[m][n], af[m], bf);
            }
        }

        // ---- end of a k-pass: shuffle top-2 fold, merge, reset ----
        if ((c & 15) == 15) {
            const int k0p = (c >> 4) << 7;
            const int kb  = k0p + kwb;
            #pragma unroll
            for (int n = 0; n < 2; n++) {
                #pragma unroll
                for (int h = 0; h < 2; h++) {
                    float v1 = 3.4e38f, v2 = 3.4e38f;
                    int   i1 = 0,       i2 = 0;
                    #pragma unroll
                    for (int m = 0; m < 4; m++) {
                        const int kA = kb + m * 16 + gid;
                        top2(__ldg(&g_csq[kA])     - 2.f * acc[m][n][h],     kA,
                             v1, i1, v2, i2);
                        top2(__ldg(&g_csq[kA + 8]) - 2.f * acc[m][n][h + 2], kA + 8,
                             v1, i1, v2, i2);
                    }
                    #pragma unroll
                    for (int off = 4; off <= 16; off <<= 1) {
                        float ov1 = __shfl_xor_sync(0xFFFFFFFFu, v1, off);
                        int   oi1 = __shfl_xor_sync(0xFFFFFFFFu, i1, off);
                        float ov2 = __shfl_xor_sync(0xFFFFFFFFu, v2, off);
                        int   oi2 = __shfl_xor_sync(0xFFFFFFFFu, i2, off);
                        top2(ov1, oi1, v1, i1, v2, i2);
                        top2(ov2, oi2, v1, i1, v2, i2);
                    }
                    if (gid == 0) {
                        const int t = twb + n * 8 + 2 * tig + h;
                        rv1[warp_k * 64 + t] = v1; ri1[warp_k * 64 + t] = i1;
                        rv2[warp_k * 64 + t] = v2; ri2[warp_k * 64 + t] = i2;
                    }
                }
            }
            #pragma unroll
            for (int m = 0; m < 4; m++)
                #pragma unroll
                for (int n = 0; n < 2; n++)
                    #pragma unroll
                    for (int r = 0; r < 4; r++) acc[m][n][r] = 0.f;
            __syncthreads();
            if (tid < TILE_T) {
                float v1 = bv1[tid], v2 = bv2[tid];
                int   i1 = bi1[tid], i2 = bi2[tid];
                top2(rv1[tid],      ri1[tid],      v1, i1, v2, i2);
                top2(rv2[tid],      ri2[tid],      v1, i1, v2, i2);
                top2(rv1[64 + tid], ri1[64 + tid], v1, i1, v2, i2);
                top2(rv2[64 + tid], ri2[64 + tid], v1, i1, v2, i2);
                bv1[tid] = v1; bi1[tid] = i1; bv2[tid] = v2; bi2[tid] = i2;
            }
        }
    }
    __syncthreads();           // bv/bi final before rescore reads

    // ---- exact fp32 rescore of top-2 candidates (raw x, raw cb) ----
    float* XSf = (float*)smb;                    // f32 staging, 32 x 72 floats
    float* rsc = rv1;                            // 128 scores
    const int p    = (tid & 127) >> 1;
    const int half = tid & 1;
    const int cand = half ? bi2[p] : bi1[p];
    const float* crow = cb + (size_t)cand * DD;
    float dot = 0.f;
    for (int dc = 0; dc < 16; dc++) {
        const int d0 = dc * 32;
        __syncthreads();
        #pragma unroll
        for (int l = 0; l < 2; l++) {            // 32d x 64t floats = 512 f4
            int e  = l * 256 + tid;
            int d  = e >> 4;
            int t4 = e & 15;
            *(float4*)&XSf[d * XROWH + t4 * 4] =
                *(const float4*)(xb + (size_t)(d0 + d) * TT + t4 * 4);
        }
        __syncthreads();
        if (tid < 128) {
            #pragma unroll
            for (int j = 0; j < 8; j++) {
                float4 cv = *(const float4*)(crow + d0 + 4 * j);
                dot = fmaf(XSf[(4 * j + 0) * XROWH + p], cv.x, dot);
                dot = fmaf(XSf[(4 * j + 1) * XROWH + p], cv.y, dot);
                dot = fmaf(XSf[(4 * j + 2) * XROWH + p], cv.z, dot);
                dot = fmaf(XSf[(4 * j + 3) * XROWH + p], cv.w, dot);
            }
        }
    }
    if (tid < 128) rsc[tid] = __ldg(&g_csq[cand]) - 2.f * dot;
    __syncthreads();
    if (tid < TILE_T) {
        float sA = rsc[2 * tid], sB = rsc[2 * tid + 1];
        int   iA = bi1[tid],     iB = bi2[tid];
        int fin = (sB < sA || (sB == sA && iB < iA)) ? iB : iA;
        bi1[tid] = fin;
        iout[(size_t)b * TT + t0 + tid] = (float)fin;
    }
    __syncthreads();

    // ---- gather quantized: t-coalesced stores ----
    float* qb = qout + (size_t)b * DD * TT + t0;
    for (int e = tid; e < DD * TILE_T; e += 256) {
        int t = e & (TILE_T - 1);
        int d = e >> 6;
        qb[(size_t)d * TT + t] = cb[(size_t)bi1[t] * DD + d];
    }
}

extern "C" void kernel_launch(void* const* d_in, const int* in_sizes, int n_in,
                              void* d_out, int out_size) {
    const float* x  = (const float*)d_in[0];   // [B, D, T] fp32
    const float* cb = (const float*)d_in[1];   // [K, D]    fp32

    float* qout = (float*)d_out;                         // [B, D, T]
    float* iout = (float*)d_out + (size_t)BB * DD * TT;  // [B, T] as float

    cudaFuncSetAttribute(vq_kernel, cudaFuncAttributeMaxDynamicSharedMemorySize,
                         SMEM_BYTES);

    __half* xh;  cudaGetSymbolAddress((void**)&xh,  g_xh);
    __half* cbh; cudaGetSymbolAddress((void**)&cbh, g_cbh);

    csq_kernel<<<(KK * 32 + 255) / 256, 256>>>(cb);
    {
        int n8 = (BB * DD * TT) / 8;
        prep_half<<<(n8 + 255) / 256, 256>>>(x, xh, n8);
    }
    {
        int n8 = (KK * DD) / 8;
        prep_half<<<(n8 + 255) / 256, 256>>>(cb, cbh, n8);
    }
    vq_kernel<<<(BB * TT) / TILE_T, 256, SMEM_BYTES>>>(x, cb, qout, iout);
}